// round 8
// baseline (speedup 1.0000x reference)
#include <cuda_runtime.h>
#include <cuda_fp16.h>
#include <cstdint>

#define K_DIM 1024
#define N_DIM 1024
#define MAX_M 65536

// ---------------------------------------------------------------------------
// Scratch (device globals — no allocation APIs allowed)
// ---------------------------------------------------------------------------
__device__ __half g_A[(size_t)MAX_M * K_DIM];
__device__ __half g_B[(size_t)N_DIM * K_DIM];
__device__ unsigned g_cnt[MAX_M / 128];   // per-row-block completion counters

__device__ __forceinline__ uint32_t smem_u32(const void* p) {
    uint32_t a;
    asm("{ .reg .u64 t; cvta.to.shared.u64 t, %1; cvt.u32.u64 %0, t; }"
        : "=r"(a) : "l"(p));
    return a;
}

__device__ __forceinline__ void cp_async16(uint32_t saddr, const void* gaddr) {
    asm volatile("cp.async.cg.shared.global [%0], [%1], 16;"
                 :: "r"(saddr), "l"(gaddr) : "memory");
}

__device__ __forceinline__ void ldsm_x4(uint32_t addr, uint32_t& r0, uint32_t& r1,
                                        uint32_t& r2, uint32_t& r3) {
    asm volatile("ldmatrix.sync.aligned.m8n8.x4.shared.b16 {%0,%1,%2,%3}, [%4];"
                 : "=r"(r0), "=r"(r1), "=r"(r2), "=r"(r3) : "r"(addr));
}

__device__ __forceinline__ void mma16816(float* c, const uint32_t* a,
                                         const uint32_t* b) {
    asm volatile(
        "mma.sync.aligned.m16n8k16.row.col.f32.f16.f16.f32 "
        "{%0,%1,%2,%3}, {%4,%5,%6,%7}, {%8,%9}, {%0,%1,%2,%3};"
        : "+f"(c[0]), "+f"(c[1]), "+f"(c[2]), "+f"(c[3])
        : "r"(a[0]), "r"(a[1]), "r"(a[2]), "r"(a[3]), "r"(b[0]), "r"(b[1]));
}

// ---------------------------------------------------------------------------
// Kernel 1: per-row logmap0 scale fused with fp16 convert of A.
// ---------------------------------------------------------------------------
__global__ void convertA_kernel(const float* __restrict__ x) {
    const int row = blockIdx.x;
    const int t = threadIdx.x;
    const float4* xr = reinterpret_cast<const float4*>(x + ((size_t)row << 10));
    float4 v = xr[t];
    v.x = (v.x == v.x) ? v.x : 0.0f;
    v.y = (v.y == v.y) ? v.y : 0.0f;
    v.z = (v.z == v.z) ? v.z : 0.0f;
    v.w = (v.w == v.w) ? v.w : 0.0f;

    float ss = v.x * v.x + v.y * v.y + v.z * v.z + v.w * v.w;
#pragma unroll
    for (int o = 16; o > 0; o >>= 1) ss += __shfl_down_sync(0xFFFFFFFFu, ss, o);
    __shared__ float ws[8];
    __shared__ float s_scale;
    if ((t & 31) == 0) ws[t >> 5] = ss;
    __syncthreads();
    if (t == 0) {
        float tt = 0.0f;
#pragma unroll
        for (int w = 0; w < 8; w++) tt += ws[w];
        float pn = fmaxf(sqrtf(tt), 1e-15f);
        float arg = fminf(pn, 0.99f - 1e-7f);
        arg = fmaxf(arg, -0.99f + 1e-7f);
        float at = 0.5f * (log1pf(arg) - log1pf(-arg));
        s_scale = at / pn;
    }
    __syncthreads();
    const float s = s_scale;

    float a[4] = {v.x, v.y, v.z, v.w};
    __half h[4];
#pragma unroll
    for (int i = 0; i < 4; i++) {
        float w = fminf(fmaxf(a[i] * s, -50.0f), 50.0f);
        h[i] = __float2half_rn(w);
    }
    __half2* ph = reinterpret_cast<__half2*>(g_A + ((size_t)row << 10));
    ph[2 * t]     = __halves2half2(h[0], h[1]);
    ph[2 * t + 1] = __halves2half2(h[2], h[3]);
}

// ---------------------------------------------------------------------------
// Kernel 2: fp16 convert of m + reset of the row-block counters.
// ---------------------------------------------------------------------------
__global__ void convertB_kernel(const float* __restrict__ m) {
    if (blockIdx.x == 0) {
        for (int i = threadIdx.x; i < MAX_M / 128; i += 256) g_cnt[i] = 0u;
    }
    const size_t i = (size_t)blockIdx.x * 256 + threadIdx.x;  // 262144 float4s
    float4 v = reinterpret_cast<const float4*>(m)[i];
    __half2* ph = reinterpret_cast<__half2*>(g_B);
    ph[2 * i]     = __halves2half2(__float2half_rn(v.x), __float2half_rn(v.y));
    ph[2 * i + 1] = __halves2half2(__float2half_rn(v.z), __float2half_rn(v.w));
}

// ---------------------------------------------------------------------------
// Kernel 3: fp16 HMMA GEMM (round-4/6 proven config: CTA 128x128, BK=64,
// 8 warps 4m x 2n, 3-stage cp.async, 96 KB SMEM, 2 CTAs/SM) with the
// expmap0/proj epilogue FUSED via threadfence-reduction: the last CTA of
// each 128-row block (rank 7 of 8 N-tiles) re-reads the block (L2-hot)
// and applies clip -> norm -> tanh scaling, warp-per-row.
// ---------------------------------------------------------------------------
#define TILE_B 16384
#define STAGE_B (2 * TILE_B)
#define NSTAGE 3
#define SMEM_TOTAL (NSTAGE * STAGE_B)   // 96 KB

__global__ __launch_bounds__(256, 2) void gemm_hmma(float* __restrict__ C) {
    extern __shared__ char smem[];
    const uint32_t sb = smem_u32(smem);
    const int tid = threadIdx.x;
    const int wid = tid >> 5, lid = tid & 31;
    const int wm = wid & 3, wn = wid >> 2;        // warp grid 4(m) x 2(n)
    const int bm = blockIdx.y << 7, bn = blockIdx.x << 7;

    auto load_stage = [&](int st, int k0) {
        const uint32_t sbase = sb + st * STAGE_B;
#pragma unroll
        for (int t = 0; t < 2; t++) {
            const __half* g = t ? g_B : g_A;
            const int rb = t ? bn : bm;
            const uint32_t sdst = sbase + t * TILE_B;
#pragma unroll
            for (int i = 0; i < 4; i++) {
                int idx = tid + (i << 8);           // 0..1023
                int r = idx >> 3;                   // 0..127
                int c16 = idx & 7;                  // 16B chunk in row
                uint32_t boff = (uint32_t)((r << 7) + (c16 << 4));
                uint32_t sw = boff ^ ((boff >> 3) & 0x70);
                cp_async16(sdst + sw,
                           g + ((size_t)(rb + r) << 10) + k0 + (c16 << 3));
            }
        }
        asm volatile("cp.async.commit_group;" ::: "memory");
    };

    const int lr = lid & 15;
    const uint32_t khalf = (uint32_t)((lid >> 4) << 4);
    uint32_t rA[2], xA[2], rB[4], xB[4];
#pragma unroll
    for (int i = 0; i < 2; i++) {
        int r = wm * 32 + i * 16 + lr;
        rA[i] = (uint32_t)(r << 7);
        xA[i] = (uint32_t)((r & 7) << 4);
    }
#pragma unroll
    for (int j = 0; j < 4; j++) {
        int r = wn * 64 + j * 16 + lr;
        rB[j] = (uint32_t)(r << 7);
        xB[j] = (uint32_t)((r & 7) << 4);
    }

    float acc[2][8][4];
#pragma unroll
    for (int i = 0; i < 2; i++)
#pragma unroll
        for (int j = 0; j < 8; j++)
#pragma unroll
            for (int q = 0; q < 4; q++) acc[i][j][q] = 0.0f;

    load_stage(0, 0);
    load_stage(1, 64);

    int st = 0;

    auto do_chunk = [&]() {
        const uint32_t stb = sb + st * STAGE_B;
        const uint32_t tA = stb, tB = stb + TILE_B;
#pragma unroll
        for (int kk = 0; kk < 4; kk++) {
            const uint32_t kb = (uint32_t)(kk * 32) + khalf;
            uint32_t a[2][4];
#pragma unroll
            for (int i = 0; i < 2; i++)
                ldsm_x4(tA + rA[i] + (kb ^ xA[i]),
                        a[i][0], a[i][1], a[i][2], a[i][3]);
            uint32_t b[8][2];
#pragma unroll
            for (int j = 0; j < 4; j++) {
                uint32_t r0, r1, r2, r3;
                ldsm_x4(tB + rB[j] + (kb ^ xB[j]), r0, r1, r2, r3);
                b[2 * j][0] = r0; b[2 * j + 1][0] = r1;
                b[2 * j][1] = r2; b[2 * j + 1][1] = r3;
            }
#pragma unroll
            for (int i = 0; i < 2; i++)
#pragma unroll
                for (int j = 0; j < 8; j++) mma16816(acc[i][j], a[i], b[j]);
        }
        st = st + 1; if (st >= NSTAGE) st = 0;
    };

    for (int c = 0; c < 15; ++c) {
        asm volatile("cp.async.wait_group 1;" ::: "memory");
        __syncthreads();
        if (c + 2 < 16) {
            int st2 = st + 2; if (st2 >= NSTAGE) st2 -= NSTAGE;
            load_stage(st2, (c + 2) << 6);
        }
        do_chunk();
    }
    asm volatile("cp.async.wait_group 0;" ::: "memory");
    __syncthreads();
    do_chunk();

    // Store raw fp32 mx (fused epilogue applies the ±1000 clip on readback).
    const int r0 = bm + wm * 32 + (lid >> 2);
    const int c0 = bn + wn * 64 + ((lid & 3) << 1);
#pragma unroll
    for (int i = 0; i < 2; i++) {
#pragma unroll
        for (int j = 0; j < 8; j++) {
            size_t base = ((size_t)(r0 + i * 16) << 10) + c0 + j * 8;
            *reinterpret_cast<float2*>(C + base) =
                make_float2(acc[i][j][0], acc[i][j][1]);
            *reinterpret_cast<float2*>(C + base + (8 << 10)) =
                make_float2(acc[i][j][2], acc[i][j][3]);
        }
    }

    // ---- fused epilogue (threadfence reduction) ----
    __threadfence();
    __shared__ unsigned s_rank;
    __syncthreads();               // all stores of this CTA issued before fence+count
    if (tid == 0) s_rank = atomicAdd(&g_cnt[blockIdx.y], 1u);
    __syncthreads();
    if (s_rank != 7u) return;
    __threadfence();               // acquire: see the other 7 CTAs' C stores

    // This CTA finalizes rows [bm, bm+128): warp-per-row, 16 rows per warp.
    for (int it = 0; it < 16; ++it) {
        const int row = bm + it * 8 + wid;
        float4* p = reinterpret_cast<float4*>(C + ((size_t)row << 10));
        float4 v[8];
        float ss = 0.0f;
#pragma unroll
        for (int j = 0; j < 8; j++) {
            float4 t = p[lid + (j << 5)];
            t.x = fminf(fmaxf(t.x, -1000.0f), 1000.0f);
            t.y = fminf(fmaxf(t.y, -1000.0f), 1000.0f);
            t.z = fminf(fmaxf(t.z, -1000.0f), 1000.0f);
            t.w = fminf(fmaxf(t.w, -1000.0f), 1000.0f);
            v[j] = t;
            ss += t.x * t.x + t.y * t.y + t.z * t.z + t.w * t.w;
        }
#pragma unroll
        for (int o = 16; o > 0; o >>= 1)
            ss += __shfl_xor_sync(0xFFFFFFFFu, ss, o);

        const float un = fmaxf(sqrtf(ss), 1e-15f);
        const float th = tanhf(un);
        float f = th / un;
        const float max_norm = (float)(1.0 - 1e-10);
        if (th > max_norm) f *= max_norm / fmaxf(th, 1e-9f);

#pragma unroll
        for (int j = 0; j < 8; j++) {
            float4 t = v[j];
            t.x *= f; t.y *= f; t.z *= f; t.w *= f;
            p[lid + (j << 5)] = t;
        }
    }
}

// ---------------------------------------------------------------------------
extern "C" void kernel_launch(void* const* d_in, const int* in_sizes, int n_in,
                              void* d_out, int out_size) {
    const float* x = (const float*)d_in[0];   // [M, 1024]
    const float* m = (const float*)d_in[1];   // [1024, 1024]
    float* out = (float*)d_out;               // [M, 1024] f32

    int M = in_sizes[0] / K_DIM;
    if (M > MAX_M) M = MAX_M;

    cudaFuncSetAttribute(gemm_hmma, cudaFuncAttributeMaxDynamicSharedMemorySize,
                         SMEM_TOTAL);

    convertA_kernel<<<M, 256>>>(x);
    convertB_kernel<<<1024, 256>>>(m);

    dim3 grid(N_DIM / 128, M / 128);
    gemm_hmma<<<grid, 256, SMEM_TOTAL>>>(out);
}

// round 9
// speedup vs baseline: 1.1786x; 1.1786x over previous
#include <cuda_runtime.h>
#include <cuda_fp16.h>
#include <cstdint>

#define K_DIM 1024
#define N_DIM 1024
#define MAX_M 65536

// ---------------------------------------------------------------------------
// Scratch (device globals — no allocation APIs allowed)
// ---------------------------------------------------------------------------
__device__ __half g_A[(size_t)MAX_M * K_DIM];
__device__ __half g_B[(size_t)N_DIM * K_DIM];

__device__ __forceinline__ uint32_t smem_u32(const void* p) {
    uint32_t a;
    asm("{ .reg .u64 t; cvta.to.shared.u64 t, %1; cvt.u32.u64 %0, t; }"
        : "=r"(a) : "l"(p));
    return a;
}

__device__ __forceinline__ void cp_async16(uint32_t saddr, const void* gaddr) {
    asm volatile("cp.async.cg.shared.global [%0], [%1], 16;"
                 :: "r"(saddr), "l"(gaddr) : "memory");
}

__device__ __forceinline__ void ldsm_x4(uint32_t addr, uint32_t& r0, uint32_t& r1,
                                        uint32_t& r2, uint32_t& r3) {
    asm volatile("ldmatrix.sync.aligned.m8n8.x4.shared.b16 {%0,%1,%2,%3}, [%4];"
                 : "=r"(r0), "=r"(r1), "=r"(r2), "=r"(r3) : "r"(addr));
}

__device__ __forceinline__ void mma16816(float* c, const uint32_t* a,
                                         const uint32_t* b) {
    asm volatile(
        "mma.sync.aligned.m16n8k16.row.col.f32.f16.f16.f32 "
        "{%0,%1,%2,%3}, {%4,%5,%6,%7}, {%8,%9}, {%0,%1,%2,%3};"
        : "+f"(c[0]), "+f"(c[1]), "+f"(c[2]), "+f"(c[3])
        : "r"(a[0]), "r"(a[1]), "r"(a[2]), "r"(a[3]), "r"(b[0]), "r"(b[1]));
}

// ---------------------------------------------------------------------------
// Kernel 1: per-row logmap0 scale fused with fp16 convert of A.
// Warp-per-row: 8 rows per 256-thread block; each lane owns 8 float4s
// (coalesced, stride 32). Norm via shfl only — no smem, no block barriers.
// ---------------------------------------------------------------------------
__global__ void convertA_kernel(const float* __restrict__ x) {
    const int wid = threadIdx.x >> 5, lid = threadIdx.x & 31;
    const int row = (blockIdx.x << 3) + wid;
    const float4* xr = reinterpret_cast<const float4*>(x + ((size_t)row << 10));

    float4 v[8];
    float ss = 0.0f;
#pragma unroll
    for (int j = 0; j < 8; j++) {
        float4 t = xr[lid + (j << 5)];
        t.x = (t.x == t.x) ? t.x : 0.0f;
        t.y = (t.y == t.y) ? t.y : 0.0f;
        t.z = (t.z == t.z) ? t.z : 0.0f;
        t.w = (t.w == t.w) ? t.w : 0.0f;
        v[j] = t;
        ss += t.x * t.x + t.y * t.y + t.z * t.z + t.w * t.w;
    }
#pragma unroll
    for (int o = 16; o > 0; o >>= 1) ss += __shfl_xor_sync(0xFFFFFFFFu, ss, o);

    float pn = fmaxf(sqrtf(ss), 1e-15f);
    float arg = fminf(pn, 0.99f - 1e-7f);
    arg = fmaxf(arg, -0.99f + 1e-7f);
    float at = 0.5f * (log1pf(arg) - log1pf(-arg));
    const float s = at / pn;

    uint2* ph = reinterpret_cast<uint2*>(g_A + ((size_t)row << 10));
#pragma unroll
    for (int j = 0; j < 8; j++) {
        float4 t = v[j];
        __half2 h0 = __halves2half2(
            __float2half_rn(fminf(fmaxf(t.x * s, -50.0f), 50.0f)),
            __float2half_rn(fminf(fmaxf(t.y * s, -50.0f), 50.0f)));
        __half2 h1 = __halves2half2(
            __float2half_rn(fminf(fmaxf(t.z * s, -50.0f), 50.0f)),
            __float2half_rn(fminf(fmaxf(t.w * s, -50.0f), 50.0f)));
        uint2 u;
        u.x = *reinterpret_cast<uint32_t*>(&h0);
        u.y = *reinterpret_cast<uint32_t*>(&h1);
        ph[lid + (j << 5)] = u;
    }
}

// ---------------------------------------------------------------------------
// Kernel 2: fp16 convert of m (1024x1024).
// ---------------------------------------------------------------------------
__global__ void convertB_kernel(const float* __restrict__ m) {
    const size_t i = (size_t)blockIdx.x * 256 + threadIdx.x;  // 262144 float4s
    float4 v = reinterpret_cast<const float4*>(m)[i];
    __half2* ph = reinterpret_cast<__half2*>(g_B);
    ph[2 * i]     = __halves2half2(__float2half_rn(v.x), __float2half_rn(v.y));
    ph[2 * i + 1] = __halves2half2(__float2half_rn(v.z), __float2half_rn(v.w));
}

// ---------------------------------------------------------------------------
// Kernel 3: single-pass fp16 HMMA GEMM (round-4/6 proven config).
// CTA tile 128x128, BK=64, 8 warps (4m x 2n), 3-stage cp.async pipeline,
// 96 KB SMEM, 2 CTAs/SM. Raw fp32 store (epilogue clips).
// ---------------------------------------------------------------------------
#define TILE_B 16384
#define STAGE_B (2 * TILE_B)
#define NSTAGE 3
#define SMEM_TOTAL (NSTAGE * STAGE_B)   // 96 KB

__global__ __launch_bounds__(256, 2) void gemm_hmma(float* __restrict__ C) {
    extern __shared__ char smem[];
    const uint32_t sb = smem_u32(smem);
    const int tid = threadIdx.x;
    const int wid = tid >> 5, lid = tid & 31;
    const int wm = wid & 3, wn = wid >> 2;        // warp grid 4(m) x 2(n)
    const int bm = blockIdx.y << 7, bn = blockIdx.x << 7;

    auto load_stage = [&](int st, int k0) {
        const uint32_t sbase = sb + st * STAGE_B;
#pragma unroll
        for (int t = 0; t < 2; t++) {
            const __half* g = t ? g_B : g_A;
            const int rb = t ? bn : bm;
            const uint32_t sdst = sbase + t * TILE_B;
#pragma unroll
            for (int i = 0; i < 4; i++) {
                int idx = tid + (i << 8);           // 0..1023
                int r = idx >> 3;                   // 0..127
                int c16 = idx & 7;                  // 16B chunk in row
                uint32_t boff = (uint32_t)((r << 7) + (c16 << 4));
                uint32_t sw = boff ^ ((boff >> 3) & 0x70);
                cp_async16(sdst + sw,
                           g + ((size_t)(rb + r) << 10) + k0 + (c16 << 3));
            }
        }
        asm volatile("cp.async.commit_group;" ::: "memory");
    };

    const int lr = lid & 15;
    const uint32_t khalf = (uint32_t)((lid >> 4) << 4);
    uint32_t rA[2], xA[2], rB[4], xB[4];
#pragma unroll
    for (int i = 0; i < 2; i++) {
        int r = wm * 32 + i * 16 + lr;
        rA[i] = (uint32_t)(r << 7);
        xA[i] = (uint32_t)((r & 7) << 4);
    }
#pragma unroll
    for (int j = 0; j < 4; j++) {
        int r = wn * 64 + j * 16 + lr;
        rB[j] = (uint32_t)(r << 7);
        xB[j] = (uint32_t)((r & 7) << 4);
    }

    float acc[2][8][4];
#pragma unroll
    for (int i = 0; i < 2; i++)
#pragma unroll
        for (int j = 0; j < 8; j++)
#pragma unroll
            for (int q = 0; q < 4; q++) acc[i][j][q] = 0.0f;

    load_stage(0, 0);
    load_stage(1, 64);

    int st = 0;

    auto do_chunk = [&]() {
        const uint32_t stb = sb + st * STAGE_B;
        const uint32_t tA = stb, tB = stb + TILE_B;
#pragma unroll
        for (int kk = 0; kk < 4; kk++) {
            const uint32_t kb = (uint32_t)(kk * 32) + khalf;
            uint32_t a[2][4];
#pragma unroll
            for (int i = 0; i < 2; i++)
                ldsm_x4(tA + rA[i] + (kb ^ xA[i]),
                        a[i][0], a[i][1], a[i][2], a[i][3]);
            uint32_t b[8][2];
#pragma unroll
            for (int j = 0; j < 4; j++) {
                uint32_t r0, r1, r2, r3;
                ldsm_x4(tB + rB[j] + (kb ^ xB[j]), r0, r1, r2, r3);
                b[2 * j][0] = r0; b[2 * j + 1][0] = r1;
                b[2 * j][1] = r2; b[2 * j + 1][1] = r3;
            }
#pragma unroll
            for (int i = 0; i < 2; i++)
#pragma unroll
                for (int j = 0; j < 8; j++) mma16816(acc[i][j], a[i], b[j]);
        }
        st = st + 1; if (st >= NSTAGE) st = 0;
    };

    for (int c = 0; c < 15; ++c) {
        asm volatile("cp.async.wait_group 1;" ::: "memory");
        __syncthreads();
        if (c + 2 < 16) {
            int st2 = st + 2; if (st2 >= NSTAGE) st2 -= NSTAGE;
            load_stage(st2, (c + 2) << 6);
        }
        do_chunk();
    }
    asm volatile("cp.async.wait_group 0;" ::: "memory");
    __syncthreads();
    do_chunk();

    // Store raw fp32 mx (epilogue applies the ±1000 clip before use).
    const int r0 = bm + wm * 32 + (lid >> 2);
    const int c0 = bn + wn * 64 + ((lid & 3) << 1);
#pragma unroll
    for (int i = 0; i < 2; i++) {
#pragma unroll
        for (int j = 0; j < 8; j++) {
            size_t base = ((size_t)(r0 + i * 16) << 10) + c0 + j * 8;
            *reinterpret_cast<float2*>(C + base) =
                make_float2(acc[i][j][0], acc[i][j][1]);
            *reinterpret_cast<float2*>(C + base + (8 << 10)) =
                make_float2(acc[i][j][2], acc[i][j][3]);
        }
    }
}

// ---------------------------------------------------------------------------
// Kernel 4 (in-place): out = proj(expmap0(clip(mx), 1), 1)
// Warp-per-row: 8 rows per 256-thread block, no smem/barriers.
// ---------------------------------------------------------------------------
__global__ void epilogue_kernel(float* __restrict__ C) {
    const int wid = threadIdx.x >> 5, lid = threadIdx.x & 31;
    const int row = (blockIdx.x << 3) + wid;
    float4* p = reinterpret_cast<float4*>(C + ((size_t)row << 10));

    float4 v[8];
    float ss = 0.0f;
#pragma unroll
    for (int j = 0; j < 8; j++) {
        float4 t = p[lid + (j << 5)];
        t.x = fminf(fmaxf(t.x, -1000.0f), 1000.0f);
        t.y = fminf(fmaxf(t.y, -1000.0f), 1000.0f);
        t.z = fminf(fmaxf(t.z, -1000.0f), 1000.0f);
        t.w = fminf(fmaxf(t.w, -1000.0f), 1000.0f);
        v[j] = t;
        ss += t.x * t.x + t.y * t.y + t.z * t.z + t.w * t.w;
    }
#pragma unroll
    for (int o = 16; o > 0; o >>= 1) ss += __shfl_xor_sync(0xFFFFFFFFu, ss, o);

    const float un = fmaxf(sqrtf(ss), 1e-15f);
    const float th = tanhf(un);
    float f = th / un;
    const float max_norm = (float)(1.0 - 1e-10);
    if (th > max_norm) f *= max_norm / fmaxf(th, 1e-9f);

#pragma unroll
    for (int j = 0; j < 8; j++) {
        float4 t = v[j];
        t.x *= f; t.y *= f; t.z *= f; t.w *= f;
        p[lid + (j << 5)] = t;
    }
}

// ---------------------------------------------------------------------------
extern "C" void kernel_launch(void* const* d_in, const int* in_sizes, int n_in,
                              void* d_out, int out_size) {
    const float* x = (const float*)d_in[0];   // [M, 1024]
    const float* m = (const float*)d_in[1];   // [1024, 1024]
    float* out = (float*)d_out;               // [M, 1024] f32

    int M = in_sizes[0] / K_DIM;
    if (M > MAX_M) M = MAX_M;

    cudaFuncSetAttribute(gemm_hmma, cudaFuncAttributeMaxDynamicSharedMemorySize,
                         SMEM_TOTAL);

    convertA_kernel<<<M / 8, 256>>>(x);
    convertB_kernel<<<1024, 256>>>(m);

    dim3 grid(N_DIM / 128, M / 128);
    gemm_hmma<<<grid, 256, SMEM_TOTAL>>>(out);

    epilogue_kernel<<<M / 8, 256>>>(out);
}

// round 10
// speedup vs baseline: 1.2608x; 1.0697x over previous
#include <cuda_runtime.h>
#include <cuda_fp16.h>
#include <cstdint>

#define K_DIM 1024
#define N_DIM 1024
#define MAX_M 65536

// ---------------------------------------------------------------------------
// Scratch (device globals — no allocation APIs allowed)
// ---------------------------------------------------------------------------
__device__ __half g_A[(size_t)MAX_M * K_DIM];
__device__ __half g_B[(size_t)N_DIM * K_DIM];

__device__ __forceinline__ uint32_t smem_u32(const void* p) {
    uint32_t a;
    asm("{ .reg .u64 t; cvta.to.shared.u64 t, %1; cvt.u32.u64 %0, t; }"
        : "=r"(a) : "l"(p));
    return a;
}

__device__ __forceinline__ void cp_async16(uint32_t saddr, const void* gaddr) {
    asm volatile("cp.async.cg.shared.global [%0], [%1], 16;"
                 :: "r"(saddr), "l"(gaddr) : "memory");
}

__device__ __forceinline__ void ldsm_x4(uint32_t addr, uint32_t& r0, uint32_t& r1,
                                        uint32_t& r2, uint32_t& r3) {
    asm volatile("ldmatrix.sync.aligned.m8n8.x4.shared.b16 {%0,%1,%2,%3}, [%4];"
                 : "=r"(r0), "=r"(r1), "=r"(r2), "=r"(r3) : "r"(addr));
}

__device__ __forceinline__ void mma16816(float* c, const uint32_t* a,
                                         const uint32_t* b) {
    asm volatile(
        "mma.sync.aligned.m16n8k16.row.col.f32.f16.f16.f32 "
        "{%0,%1,%2,%3}, {%4,%5,%6,%7}, {%8,%9}, {%0,%1,%2,%3};"
        : "+f"(c[0]), "+f"(c[1]), "+f"(c[2]), "+f"(c[3])
        : "r"(a[0]), "r"(a[1]), "r"(a[2]), "r"(a[3]), "r"(b[0]), "r"(b[1]));
}

#define CLUSTER_SYNC_ASM() do {                                         \
    asm volatile("barrier.cluster.arrive.aligned;" ::: "memory");       \
    asm volatile("barrier.cluster.wait.aligned;" ::: "memory");         \
} while (0)

// ---------------------------------------------------------------------------
// Kernel 1: per-row logmap0 scale fused with fp16 convert of A.
// Warp-per-row, no smem/barriers (proven round 9).
// ---------------------------------------------------------------------------
__global__ void convertA_kernel(const float* __restrict__ x) {
    const int wid = threadIdx.x >> 5, lid = threadIdx.x & 31;
    const int row = (blockIdx.x << 3) + wid;
    const float4* xr = reinterpret_cast<const float4*>(x + ((size_t)row << 10));

    float4 v[8];
    float ss = 0.0f;
#pragma unroll
    for (int j = 0; j < 8; j++) {
        float4 t = xr[lid + (j << 5)];
        t.x = (t.x == t.x) ? t.x : 0.0f;
        t.y = (t.y == t.y) ? t.y : 0.0f;
        t.z = (t.z == t.z) ? t.z : 0.0f;
        t.w = (t.w == t.w) ? t.w : 0.0f;
        v[j] = t;
        ss += t.x * t.x + t.y * t.y + t.z * t.z + t.w * t.w;
    }
#pragma unroll
    for (int o = 16; o > 0; o >>= 1) ss += __shfl_xor_sync(0xFFFFFFFFu, ss, o);

    float pn = fmaxf(sqrtf(ss), 1e-15f);
    float arg = fminf(pn, 0.99f - 1e-7f);
    arg = fmaxf(arg, -0.99f + 1e-7f);
    float at = 0.5f * (log1pf(arg) - log1pf(-arg));
    const float s = at / pn;

    uint2* ph = reinterpret_cast<uint2*>(g_A + ((size_t)row << 10));
#pragma unroll
    for (int j = 0; j < 8; j++) {
        float4 t = v[j];
        __half2 h0 = __halves2half2(
            __float2half_rn(fminf(fmaxf(t.x * s, -50.0f), 50.0f)),
            __float2half_rn(fminf(fmaxf(t.y * s, -50.0f), 50.0f)));
        __half2 h1 = __halves2half2(
            __float2half_rn(fminf(fmaxf(t.z * s, -50.0f), 50.0f)),
            __float2half_rn(fminf(fmaxf(t.w * s, -50.0f), 50.0f)));
        uint2 u;
        u.x = *reinterpret_cast<uint32_t*>(&h0);
        u.y = *reinterpret_cast<uint32_t*>(&h1);
        ph[lid + (j << 5)] = u;
    }
}

// ---------------------------------------------------------------------------
// Kernel 2: fp16 convert of m (1024x1024).
// ---------------------------------------------------------------------------
__global__ void convertB_kernel(const float* __restrict__ m) {
    const size_t i = (size_t)blockIdx.x * 256 + threadIdx.x;  // 262144 float4s
    float4 v = reinterpret_cast<const float4*>(m)[i];
    __half2* ph = reinterpret_cast<__half2*>(g_B);
    ph[2 * i]     = __halves2half2(__float2half_rn(v.x), __float2half_rn(v.y));
    ph[2 * i + 1] = __halves2half2(__float2half_rn(v.z), __float2half_rn(v.w));
}

// ---------------------------------------------------------------------------
// Kernel 3: fp16 HMMA GEMM (round-4/6 proven mainloop: CTA 128x128, BK=64,
// 8 warps 4m x 2n, 3-stage cp.async, 96 KB SMEM, 2 CTAs/SM) with the
// expmap0/proj epilogue fused via an 8-CTA CLUSTER spanning N=1024:
// per-CTA row-sumsq partials -> DSMEM exchange -> tanh scale -> final store.
// Epilogue scratch aliases stage-0 SMEM (guarded by cluster.sync #1):
//   floats [0..255]    rowpart[2][128]  (per-wn partials)
//   floats [256..1279] clusterbuf[8][128] (peer partials, indexed by src rank)
//   floats [1280..1407] f[128] (final per-row scale)
// ---------------------------------------------------------------------------
#define TILE_B 16384
#define STAGE_B (2 * TILE_B)
#define NSTAGE 3
#define SMEM_TOTAL (NSTAGE * STAGE_B)   // 96 KB
#define CLUSTER_X 8

__global__ __launch_bounds__(256, 2) void gemm_hmma(float* __restrict__ C) {
    extern __shared__ char smem[];
    const uint32_t sb = smem_u32(smem);
    const int tid = threadIdx.x;
    const int wid = tid >> 5, lid = tid & 31;
    const int wm = wid & 3, wn = wid >> 2;        // warp grid 4(m) x 2(n)
    const int bm = blockIdx.y << 7, bn = blockIdx.x << 7;

    auto load_stage = [&](int st, int k0) {
        const uint32_t sbase = sb + st * STAGE_B;
#pragma unroll
        for (int t = 0; t < 2; t++) {
            const __half* g = t ? g_B : g_A;
            const int rb = t ? bn : bm;
            const uint32_t sdst = sbase + t * TILE_B;
#pragma unroll
            for (int i = 0; i < 4; i++) {
                int idx = tid + (i << 8);           // 0..1023
                int r = idx >> 3;                   // 0..127
                int c16 = idx & 7;                  // 16B chunk in row
                uint32_t boff = (uint32_t)((r << 7) + (c16 << 4));
                uint32_t sw = boff ^ ((boff >> 3) & 0x70);
                cp_async16(sdst + sw,
                           g + ((size_t)(rb + r) << 10) + k0 + (c16 << 3));
            }
        }
        asm volatile("cp.async.commit_group;" ::: "memory");
    };

    const int lr = lid & 15;
    const uint32_t khalf = (uint32_t)((lid >> 4) << 4);
    uint32_t rA[2], xA[2], rB[4], xB[4];
#pragma unroll
    for (int i = 0; i < 2; i++) {
        int r = wm * 32 + i * 16 + lr;
        rA[i] = (uint32_t)(r << 7);
        xA[i] = (uint32_t)((r & 7) << 4);
    }
#pragma unroll
    for (int j = 0; j < 4; j++) {
        int r = wn * 64 + j * 16 + lr;
        rB[j] = (uint32_t)(r << 7);
        xB[j] = (uint32_t)((r & 7) << 4);
    }

    float acc[2][8][4];
#pragma unroll
    for (int i = 0; i < 2; i++)
#pragma unroll
        for (int j = 0; j < 8; j++)
#pragma unroll
            for (int q = 0; q < 4; q++) acc[i][j][q] = 0.0f;

    load_stage(0, 0);
    load_stage(1, 64);

    int st = 0;

    auto do_chunk = [&]() {
        const uint32_t stb = sb + st * STAGE_B;
        const uint32_t tA = stb, tB = stb + TILE_B;
#pragma unroll
        for (int kk = 0; kk < 4; kk++) {
            const uint32_t kb = (uint32_t)(kk * 32) + khalf;
            uint32_t a[2][4];
#pragma unroll
            for (int i = 0; i < 2; i++)
                ldsm_x4(tA + rA[i] + (kb ^ xA[i]),
                        a[i][0], a[i][1], a[i][2], a[i][3]);
            uint32_t b[8][2];
#pragma unroll
            for (int j = 0; j < 4; j++) {
                uint32_t r0, r1, r2, r3;
                ldsm_x4(tB + rB[j] + (kb ^ xB[j]), r0, r1, r2, r3);
                b[2 * j][0] = r0; b[2 * j + 1][0] = r1;
                b[2 * j][1] = r2; b[2 * j + 1][1] = r3;
            }
#pragma unroll
            for (int i = 0; i < 2; i++)
#pragma unroll
                for (int j = 0; j < 8; j++) mma16816(acc[i][j], a[i], b[j]);
        }
        st = st + 1; if (st >= NSTAGE) st = 0;
    };

    for (int c = 0; c < 15; ++c) {
        asm volatile("cp.async.wait_group 1;" ::: "memory");
        __syncthreads();
        if (c + 2 < 16) {
            int st2 = st + 2; if (st2 >= NSTAGE) st2 -= NSTAGE;
            load_stage(st2, (c + 2) << 6);
        }
        do_chunk();
    }
    asm volatile("cp.async.wait_group 0;" ::: "memory");
    __syncthreads();
    do_chunk();

    // ======================= fused cluster epilogue =======================
    float* sp = reinterpret_cast<float*>(smem);

    // 1) clip acc to ±1000 (mx clip), keep clipped values for norm AND store.
#pragma unroll
    for (int i = 0; i < 2; i++)
#pragma unroll
        for (int j = 0; j < 8; j++)
#pragma unroll
            for (int q = 0; q < 4; q++)
                acc[i][j][q] = fminf(fmaxf(acc[i][j][q], -1000.0f), 1000.0f);

    // 2) all warps done with stage smem -> safe to reuse stage-0 region.
    __syncthreads();

    // 3) per-row sumsq partials over this CTA's 128 columns.
    //    q01 -> local row wm*32 + i*16 + (lid>>2); q23 -> +8.
#pragma unroll
    for (int i = 0; i < 2; i++) {
        float s01 = 0.0f, s23 = 0.0f;
#pragma unroll
        for (int j = 0; j < 8; j++) {
            s01 += acc[i][j][0] * acc[i][j][0] + acc[i][j][1] * acc[i][j][1];
            s23 += acc[i][j][2] * acc[i][j][2] + acc[i][j][3] * acc[i][j][3];
        }
        s01 += __shfl_xor_sync(0xFFFFFFFFu, s01, 1);
        s01 += __shfl_xor_sync(0xFFFFFFFFu, s01, 2);
        s23 += __shfl_xor_sync(0xFFFFFFFFu, s23, 1);
        s23 += __shfl_xor_sync(0xFFFFFFFFu, s23, 2);
        if ((lid & 3) == 0) {
            int lrow = wm * 32 + i * 16 + (lid >> 2);
            sp[wn * 128 + lrow] = s01;          // rowpart[wn][lrow]
            sp[wn * 128 + lrow + 8] = s23;
        }
    }
    __syncthreads();

    // 4) cluster barrier #1: every CTA past its mainloop; clusterbuf region
    //    (aliasing stage-0) is now safe for remote writes.
    CLUSTER_SYNC_ASM();

    // 5) broadcast this CTA's 128 partials into every cluster CTA's buffer
    //    slot [myrank][r].
    uint32_t myrank;
    asm("mov.u32 %0, %%cluster_ctarank;" : "=r"(myrank));
    if (tid < 128) {
        float val = sp[tid] + sp[128 + tid];
        uint32_t laddr = sb + (256 + myrank * 128 + tid) * 4;
#pragma unroll
        for (int rk = 0; rk < CLUSTER_X; rk++) {
            uint32_t raddr;
            asm("mapa.shared::cluster.u32 %0, %1, %2;"
                : "=r"(raddr) : "r"(laddr), "r"(rk));
            asm volatile("st.shared::cluster.f32 [%0], %1;"
                         :: "r"(raddr), "f"(val) : "memory");
        }
    }

    // 6) cluster barrier #2: all partials delivered.
    CLUSTER_SYNC_ASM();

    // 7) per-row scale f = tanh(||row||)/||row|| (+proj max-norm guard).
    if (tid < 128) {
        float ss = 0.0f;
#pragma unroll
        for (int rk = 0; rk < CLUSTER_X; rk++) ss += sp[256 + rk * 128 + tid];
        const float un = fmaxf(sqrtf(ss), 1e-15f);
        const float th = tanhf(un);
        float f = th / un;
        const float max_norm = (float)(1.0 - 1e-10);
        if (th > max_norm) f *= max_norm / fmaxf(th, 1e-9f);
        sp[1280 + tid] = f;
    }
    __syncthreads();

    // 8) scaled final store (this IS the output; no separate epilogue pass).
    const int r0 = bm + wm * 32 + (lid >> 2);
    const int lrow0 = wm * 32 + (lid >> 2);
    const int c0 = bn + wn * 64 + ((lid & 3) << 1);
#pragma unroll
    for (int i = 0; i < 2; i++) {
        const float f01 = sp[1280 + lrow0 + i * 16];
        const float f23 = sp[1280 + lrow0 + i * 16 + 8];
#pragma unroll
        for (int j = 0; j < 8; j++) {
            size_t base = ((size_t)(r0 + i * 16) << 10) + c0 + j * 8;
            *reinterpret_cast<float2*>(C + base) =
                make_float2(acc[i][j][0] * f01, acc[i][j][1] * f01);
            *reinterpret_cast<float2*>(C + base + (8 << 10)) =
                make_float2(acc[i][j][2] * f23, acc[i][j][3] * f23);
        }
    }
}

// ---------------------------------------------------------------------------
extern "C" void kernel_launch(void* const* d_in, const int* in_sizes, int n_in,
                              void* d_out, int out_size) {
    const float* x = (const float*)d_in[0];   // [M, 1024]
    const float* m = (const float*)d_in[1];   // [1024, 1024]
    float* out = (float*)d_out;               // [M, 1024] f32

    int M = in_sizes[0] / K_DIM;
    if (M > MAX_M) M = MAX_M;

    cudaFuncSetAttribute(gemm_hmma, cudaFuncAttributeMaxDynamicSharedMemorySize,
                         SMEM_TOTAL);

    convertA_kernel<<<M / 8, 256>>>(x);
    convertB_kernel<<<1024, 256>>>(m);

    cudaLaunchConfig_t cfg = {};
    cfg.gridDim = dim3(N_DIM / 128, M / 128, 1);   // x=8 tiles = one cluster/row-block
    cfg.blockDim = dim3(256, 1, 1);
    cfg.dynamicSmemBytes = SMEM_TOTAL;
    cfg.stream = 0;
    cudaLaunchAttribute attrs[1];
    attrs[0].id = cudaLaunchAttributeClusterDimension;
    attrs[0].val.clusterDim.x = CLUSTER_X;
    attrs[0].val.clusterDim.y = 1;
    attrs[0].val.clusterDim.z = 1;
    cfg.attrs = attrs;
    cfg.numAttrs = 1;
    cudaLaunchKernelEx(&cfg, gemm_hmma, out);
}

// round 11
// speedup vs baseline: 1.3179x; 1.0453x over previous
#include <cuda_runtime.h>
#include <cuda_fp16.h>
#include <cstdint>

#define K_DIM 1024
#define N_DIM 1024
#define MAX_M 65536

// ---------------------------------------------------------------------------
// Scratch (device globals — no allocation APIs allowed)
// ---------------------------------------------------------------------------
__device__ __half g_A[(size_t)MAX_M * K_DIM];
__device__ __half g_B[(size_t)N_DIM * K_DIM];

__device__ __forceinline__ uint32_t smem_u32(const void* p) {
    uint32_t a;
    asm("{ .reg .u64 t; cvta.to.shared.u64 t, %1; cvt.u32.u64 %0, t; }"
        : "=r"(a) : "l"(p));
    return a;
}

__device__ __forceinline__ void cp_async16(uint32_t saddr, const void* gaddr) {
    asm volatile("cp.async.cg.shared.global [%0], [%1], 16;"
                 :: "r"(saddr), "l"(gaddr) : "memory");
}

__device__ __forceinline__ void ldsm_x4(uint32_t addr, uint32_t& r0, uint32_t& r1,
                                        uint32_t& r2, uint32_t& r3) {
    asm volatile("ldmatrix.sync.aligned.m8n8.x4.shared.b16 {%0,%1,%2,%3}, [%4];"
                 : "=r"(r0), "=r"(r1), "=r"(r2), "=r"(r3) : "r"(addr));
}

__device__ __forceinline__ void mma16816(float* c, const uint32_t* a,
                                         const uint32_t* b) {
    asm volatile(
        "mma.sync.aligned.m16n8k16.row.col.f32.f16.f16.f32 "
        "{%0,%1,%2,%3}, {%4,%5,%6,%7}, {%8,%9}, {%0,%1,%2,%3};"
        : "+f"(c[0]), "+f"(c[1]), "+f"(c[2]), "+f"(c[3])
        : "r"(a[0]), "r"(a[1]), "r"(a[2]), "r"(a[3]), "r"(b[0]), "r"(b[1]));
}

#define CLUSTER_SYNC_ASM() do {                                         \
    asm volatile("barrier.cluster.arrive.aligned;" ::: "memory");       \
    asm volatile("barrier.cluster.wait.aligned;" ::: "memory");         \
} while (0)

// ---------------------------------------------------------------------------
// Kernel 1: fp16 convert of m (1024x1024).
// ---------------------------------------------------------------------------
__global__ void convertB_kernel(const float* __restrict__ m) {
    const size_t i = (size_t)blockIdx.x * 256 + threadIdx.x;  // 262144 float4s
    float4 v = reinterpret_cast<const float4*>(m)[i];
    __half2* ph = reinterpret_cast<__half2*>(g_B);
    ph[2 * i]     = __halves2half2(__float2half_rn(v.x), __float2half_rn(v.y));
    ph[2 * i + 1] = __halves2half2(__float2half_rn(v.z), __float2half_rn(v.w));
}

// ---------------------------------------------------------------------------
// Kernel 2: fully-fused GEMM.
//  PROLOGUE (per cluster, overlapped with co-resident CTA's mainloop):
//    CTA rank r converts x rows [bm+16r, bm+16r+16) -> logmap0-scaled fp16
//    g_A (exact round-9 warp-per-row arithmetic), threadfence, cluster.sync.
//  MAINLOOP: proven 128x128 BK=64 HMMA, 3-stage cp.async, 2 CTAs/SM.
//  EPILOGUE (proven round 10): cluster-wide row-sumsq exchange via DSMEM,
//    tanh scale, direct final store.
// ---------------------------------------------------------------------------
#define TILE_B 16384
#define STAGE_B (2 * TILE_B)
#define NSTAGE 3
#define SMEM_TOTAL (NSTAGE * STAGE_B)   // 96 KB
#define CLUSTER_X 8

__global__ __launch_bounds__(256, 2) void gemm_hmma(float* __restrict__ C,
                                                    const float* __restrict__ X) {
    extern __shared__ char smem[];
    const uint32_t sb = smem_u32(smem);
    const int tid = threadIdx.x;
    const int wid = tid >> 5, lid = tid & 31;
    const int wm = wid & 3, wn = wid >> 2;        // warp grid 4(m) x 2(n)
    const int bm = blockIdx.y << 7, bn = blockIdx.x << 7;

    uint32_t myrank;
    asm("mov.u32 %0, %%cluster_ctarank;" : "=r"(myrank));

    // ===================== fused convertA prologue =====================
    // This CTA converts 16 rows: bm + myrank*16 + {wid*2, wid*2+1}.
    {
#pragma unroll
        for (int rr = 0; rr < 2; rr++) {
            const int row = bm + (int)(myrank << 4) + (wid << 1) + rr;
            const float4* xr =
                reinterpret_cast<const float4*>(X + ((size_t)row << 10));
            float4 v[8];
            float ss = 0.0f;
#pragma unroll
            for (int j = 0; j < 8; j++) {
                float4 t = xr[lid + (j << 5)];
                t.x = (t.x == t.x) ? t.x : 0.0f;
                t.y = (t.y == t.y) ? t.y : 0.0f;
                t.z = (t.z == t.z) ? t.z : 0.0f;
                t.w = (t.w == t.w) ? t.w : 0.0f;
                v[j] = t;
                ss += t.x * t.x + t.y * t.y + t.z * t.z + t.w * t.w;
            }
#pragma unroll
            for (int o = 16; o > 0; o >>= 1)
                ss += __shfl_xor_sync(0xFFFFFFFFu, ss, o);

            float pn = fmaxf(sqrtf(ss), 1e-15f);
            float arg = fminf(pn, 0.99f - 1e-7f);
            arg = fmaxf(arg, -0.99f + 1e-7f);
            float at = 0.5f * (log1pf(arg) - log1pf(-arg));
            const float s = at / pn;

            uint2* ph = reinterpret_cast<uint2*>(g_A + ((size_t)row << 10));
#pragma unroll
            for (int j = 0; j < 8; j++) {
                float4 t = v[j];
                __half2 h0 = __halves2half2(
                    __float2half_rn(fminf(fmaxf(t.x * s, -50.0f), 50.0f)),
                    __float2half_rn(fminf(fmaxf(t.y * s, -50.0f), 50.0f)));
                __half2 h1 = __halves2half2(
                    __float2half_rn(fminf(fmaxf(t.z * s, -50.0f), 50.0f)),
                    __float2half_rn(fminf(fmaxf(t.w * s, -50.0f), 50.0f)));
                uint2 u;
                u.x = *reinterpret_cast<uint32_t*>(&h0);
                u.y = *reinterpret_cast<uint32_t*>(&h1);
                ph[lid + (j << 5)] = u;
            }
        }
    }
    __threadfence();          // make g_A writes GPU-visible before peers read
    CLUSTER_SYNC_ASM();       // all 128 rows of this block converted

    // ========================== GEMM mainloop ==========================
    auto load_stage = [&](int st, int k0) {
        const uint32_t sbase = sb + st * STAGE_B;
#pragma unroll
        for (int t = 0; t < 2; t++) {
            const __half* g = t ? g_B : g_A;
            const int rb = t ? bn : bm;
            const uint32_t sdst = sbase + t * TILE_B;
#pragma unroll
            for (int i = 0; i < 4; i++) {
                int idx = tid + (i << 8);           // 0..1023
                int r = idx >> 3;                   // 0..127
                int c16 = idx & 7;                  // 16B chunk in row
                uint32_t boff = (uint32_t)((r << 7) + (c16 << 4));
                uint32_t sw = boff ^ ((boff >> 3) & 0x70);
                cp_async16(sdst + sw,
                           g + ((size_t)(rb + r) << 10) + k0 + (c16 << 3));
            }
        }
        asm volatile("cp.async.commit_group;" ::: "memory");
    };

    const int lr = lid & 15;
    const uint32_t khalf = (uint32_t)((lid >> 4) << 4);
    uint32_t rA[2], xA[2], rB[4], xB[4];
#pragma unroll
    for (int i = 0; i < 2; i++) {
        int r = wm * 32 + i * 16 + lr;
        rA[i] = (uint32_t)(r << 7);
        xA[i] = (uint32_t)((r & 7) << 4);
    }
#pragma unroll
    for (int j = 0; j < 4; j++) {
        int r = wn * 64 + j * 16 + lr;
        rB[j] = (uint32_t)(r << 7);
        xB[j] = (uint32_t)((r & 7) << 4);
    }

    float acc[2][8][4];
#pragma unroll
    for (int i = 0; i < 2; i++)
#pragma unroll
        for (int j = 0; j < 8; j++)
#pragma unroll
            for (int q = 0; q < 4; q++) acc[i][j][q] = 0.0f;

    load_stage(0, 0);
    load_stage(1, 64);

    int st = 0;

    auto do_chunk = [&]() {
        const uint32_t stb = sb + st * STAGE_B;
        const uint32_t tA = stb, tB = stb + TILE_B;
#pragma unroll
        for (int kk = 0; kk < 4; kk++) {
            const uint32_t kb = (uint32_t)(kk * 32) + khalf;
            uint32_t a[2][4];
#pragma unroll
            for (int i = 0; i < 2; i++)
                ldsm_x4(tA + rA[i] + (kb ^ xA[i]),
                        a[i][0], a[i][1], a[i][2], a[i][3]);
            uint32_t b[8][2];
#pragma unroll
            for (int j = 0; j < 4; j++) {
                uint32_t r0, r1, r2, r3;
                ldsm_x4(tB + rB[j] + (kb ^ xB[j]), r0, r1, r2, r3);
                b[2 * j][0] = r0; b[2 * j + 1][0] = r1;
                b[2 * j][1] = r2; b[2 * j + 1][1] = r3;
            }
#pragma unroll
            for (int i = 0; i < 2; i++)
#pragma unroll
                for (int j = 0; j < 8; j++) mma16816(acc[i][j], a[i], b[j]);
        }
        st = st + 1; if (st >= NSTAGE) st = 0;
    };

    for (int c = 0; c < 15; ++c) {
        asm volatile("cp.async.wait_group 1;" ::: "memory");
        __syncthreads();
        if (c + 2 < 16) {
            int st2 = st + 2; if (st2 >= NSTAGE) st2 -= NSTAGE;
            load_stage(st2, (c + 2) << 6);
        }
        do_chunk();
    }
    asm volatile("cp.async.wait_group 0;" ::: "memory");
    __syncthreads();
    do_chunk();

    // ======================= fused cluster epilogue =======================
    float* sp = reinterpret_cast<float*>(smem);

#pragma unroll
    for (int i = 0; i < 2; i++)
#pragma unroll
        for (int j = 0; j < 8; j++)
#pragma unroll
            for (int q = 0; q < 4; q++)
                acc[i][j][q] = fminf(fmaxf(acc[i][j][q], -1000.0f), 1000.0f);

    __syncthreads();    // done with stage smem

#pragma unroll
    for (int i = 0; i < 2; i++) {
        float s01 = 0.0f, s23 = 0.0f;
#pragma unroll
        for (int j = 0; j < 8; j++) {
            s01 += acc[i][j][0] * acc[i][j][0] + acc[i][j][1] * acc[i][j][1];
            s23 += acc[i][j][2] * acc[i][j][2] + acc[i][j][3] * acc[i][j][3];
        }
        s01 += __shfl_xor_sync(0xFFFFFFFFu, s01, 1);
        s01 += __shfl_xor_sync(0xFFFFFFFFu, s01, 2);
        s23 += __shfl_xor_sync(0xFFFFFFFFu, s23, 1);
        s23 += __shfl_xor_sync(0xFFFFFFFFu, s23, 2);
        if ((lid & 3) == 0) {
            int lrow = wm * 32 + i * 16 + (lid >> 2);
            sp[wn * 128 + lrow] = s01;
            sp[wn * 128 + lrow + 8] = s23;
        }
    }
    __syncthreads();

    CLUSTER_SYNC_ASM();      // clusterbuf (stage-0 alias) safe everywhere

    if (tid < 128) {
        float val = sp[tid] + sp[128 + tid];
        uint32_t laddr = sb + (256 + myrank * 128 + tid) * 4;
#pragma unroll
        for (int rk = 0; rk < CLUSTER_X; rk++) {
            uint32_t raddr;
            asm("mapa.shared::cluster.u32 %0, %1, %2;"
                : "=r"(raddr) : "r"(laddr), "r"(rk));
            asm volatile("st.shared::cluster.f32 [%0], %1;"
                         :: "r"(raddr), "f"(val) : "memory");
        }
    }

    CLUSTER_SYNC_ASM();      // all partials delivered

    if (tid < 128) {
        float ss = 0.0f;
#pragma unroll
        for (int rk = 0; rk < CLUSTER_X; rk++) ss += sp[256 + rk * 128 + tid];
        const float un = fmaxf(sqrtf(ss), 1e-15f);
        const float th = tanhf(un);
        float f = th / un;
        const float max_norm = (float)(1.0 - 1e-10);
        if (th > max_norm) f *= max_norm / fmaxf(th, 1e-9f);
        sp[1280 + tid] = f;
    }
    __syncthreads();

    const int r0 = bm + wm * 32 + (lid >> 2);
    const int lrow0 = wm * 32 + (lid >> 2);
    const int c0 = bn + wn * 64 + ((lid & 3) << 1);
#pragma unroll
    for (int i = 0; i < 2; i++) {
        const float f01 = sp[1280 + lrow0 + i * 16];
        const float f23 = sp[1280 + lrow0 + i * 16 + 8];
#pragma unroll
        for (int j = 0; j < 8; j++) {
            size_t base = ((size_t)(r0 + i * 16) << 10) + c0 + j * 8;
            *reinterpret_cast<float2*>(C + base) =
                make_float2(acc[i][j][0] * f01, acc[i][j][1] * f01);
            *reinterpret_cast<float2*>(C + base + (8 << 10)) =
                make_float2(acc[i][j][2] * f23, acc[i][j][3] * f23);
        }
    }
}

// ---------------------------------------------------------------------------
extern "C" void kernel_launch(void* const* d_in, const int* in_sizes, int n_in,
                              void* d_out, int out_size) {
    const float* x = (const float*)d_in[0];   // [M, 1024]
    const float* m = (const float*)d_in[1];   // [1024, 1024]
    float* out = (float*)d_out;               // [M, 1024] f32

    int M = in_sizes[0] / K_DIM;
    if (M > MAX_M) M = MAX_M;

    cudaFuncSetAttribute(gemm_hmma, cudaFuncAttributeMaxDynamicSharedMemorySize,
                         SMEM_TOTAL);

    convertB_kernel<<<1024, 256>>>(m);

    cudaLaunchConfig_t cfg = {};
    cfg.gridDim = dim3(N_DIM / 128, M / 128, 1);   // x=8 tiles = one cluster/row-block
    cfg.blockDim = dim3(256, 1, 1);
    cfg.dynamicSmemBytes = SMEM_TOTAL;
    cfg.stream = 0;
    cudaLaunchAttribute attrs[1];
    attrs[0].id = cudaLaunchAttributeClusterDimension;
    attrs[0].val.clusterDim.x = CLUSTER_X;
    attrs[0].val.clusterDim.y = 1;
    attrs[0].val.clusterDim.z = 1;
    cfg.attrs = attrs;
    cfg.numAttrs = 1;
    cudaLaunchKernelEx(&cfg, gemm_hmma, out, x);
}